// round 14
// baseline (speedup 1.0000x reference)
#include <cuda_runtime.h>

#define T_FRAMES 60
#define HID 32
#define NG 128          // 4*HID gate rows
#define EPSF 1e-5f
#define FULLM 0xffffffffu
#define LEAD 16         // frames in chunk A

// per-frame gate pre-activations, TRANSPOSED layout [t][e*4+g]
// (i/f/o entries pre-scaled by 0.5; g entries raw)
__device__ float g_gx[T_FRAMES * NG];
__device__ int   g_flag[LEAD];
__device__ int   g_done = 0;

__device__ __forceinline__ float tanha(float x) {
    float r; asm("tanh.approx.f32 %0, %1;" : "=f"(r) : "f"(x)); return r;
}
__device__ __forceinline__ int ld_acquire_gpu(const int* p) {
    int v; asm volatile("ld.acquire.gpu.global.b32 %0, [%1];" : "=r"(v) : "l"(p)); return v;
}

// ---------------------------------------------------------------------------
// Fused kernel: blocks 0..59 = per-frame MLP+LN+W_ih matvec (parallel),
// block 60 = recurrence + output head. One wave (61 blocks < 148 SMs).
// Seq block overlaps steps 0..15 with the tail of the frame phase.
// ---------------------------------------------------------------------------
__global__ void __launch_bounds__(128, 1) fused_kernel(
    const float* __restrict__ x,
    const float* __restrict__ w00, const float* __restrict__ b00,
    const float* __restrict__ w01, const float* __restrict__ b01,
    const float* __restrict__ lng, const float* __restrict__ lnb,
    const float* __restrict__ wih, const float* __restrict__ bih,
    const float* __restrict__ bhh,
    const float* __restrict__ whh,
    const float* __restrict__ bng, const float* __restrict__ bnb,
    const float* __restrict__ w10, const float* __restrict__ b10,
    const float* __restrict__ w11, const float* __restrict__ b11,
    const float* __restrict__ w12, const float* __restrict__ b12,
    float* __restrict__ out)
{
    const int tid  = threadIdx.x;
    const int wid  = tid >> 5;
    const int lane = tid & 31;

    if (blockIdx.x < T_FRAMES) {
        // =================== frame path (parallel over t) ===================
        const int t = blockIdx.x;

        __shared__ float sx[64];
        __shared__ float sf1[64];
        __shared__ float sf2[64];
        __shared__ float sfn[64];
        __shared__ float s_mu, s_rstd;

        if (tid < 64) sx[tid] = (tid < 63) ? x[t * 63 + tid] : 0.0f;
        __syncthreads();

        // Layer 0: 63 rows, 2-way split-k (pair = adjacent lanes, same warp)
        {
            const int r    = tid >> 1;
            const int half = tid & 1;
            float acc = 0.0f;
            if (r < 63) {
                const float* wr = w00 + r * 63;
                if (half == 0) {
                    #pragma unroll
                    for (int k = 0; k < 32; k++) acc = fmaf(wr[k], sx[k], acc);
                } else {
                    #pragma unroll
                    for (int k = 32; k < 63; k++) acc = fmaf(wr[k], sx[k], acc);
                }
            }
            acc += __shfl_xor_sync(FULLM, acc, 1);
            if (r < 63 && half == 0) sf1[r] = fmaxf(acc + b00[r], 0.0f);
            if (tid == 126) sf1[63] = 0.0f;
        }
        __syncthreads();

        // Layer 1: 64 rows, 2-way split-k
        {
            const int r    = tid >> 1;
            const int half = tid & 1;
            const float* wr = w01 + r * 63;
            float acc = 0.0f;
            if (half == 0) {
                #pragma unroll
                for (int k = 0; k < 32; k++) acc = fmaf(wr[k], sf1[k], acc);
            } else {
                #pragma unroll
                for (int k = 32; k < 63; k++) acc = fmaf(wr[k], sf1[k], acc);
            }
            acc += __shfl_xor_sync(FULLM, acc, 1);
            if (half == 0) sf2[r] = fmaxf(acc + b01[r], 0.0f);
        }
        __syncthreads();

        if (tid < 32) {
            float v0 = sf2[tid], v1 = sf2[tid + 32];
            float s = v0 + v1;
            float q = v0 * v0 + v1 * v1;
            #pragma unroll
            for (int o = 16; o > 0; o >>= 1) {
                s += __shfl_xor_sync(FULLM, s, o);
                q += __shfl_xor_sync(FULLM, q, o);
            }
            if (tid == 0) {
                float mu  = s * (1.0f / 64.0f);
                float var = q * (1.0f / 64.0f) - mu * mu;
                s_mu   = mu;
                s_rstd = rsqrtf(var + EPSF);
            }
        }
        __syncthreads();

        if (tid < 64)
            sfn[tid] = (sf2[tid] - s_mu) * s_rstd * lng[tid] + lnb[tid];
        __syncthreads();

        {
            float acc = bih[tid] + bhh[tid];
            const float* wr = wih + tid * 64;
            #pragma unroll
            for (int k = 0; k < 64; k++) acc = fmaf(wr[k], sfn[k], acc);
            const int gr = tid >> 5;
            float scale = (gr == 2) ? 1.0f : 0.5f;
            g_gx[t * NG + (tid & 31) * 4 + gr] = acc * scale;  // transposed
        }
        __syncthreads();
        if (tid == 0) {
            __threadfence();
            if (t < LEAD) atomicExch(&g_flag[t], 1);
            atomicAdd(&g_done, 1);
        }
        return;
    }

    // ======================= sequential path (block 60) =====================
    // lane mapping: element e = 8*wid + (lane>>2), gate g = lane&3.
    // Warp w owns all four gates of its 8 elements; c/h update is warp-local
    // (3 parallel shfl_xor); only h crosses warps (one STS + one BAR / step).
    __shared__ float sgx[T_FRAMES * NG];              // 30 KB staged gx
    __shared__ __align__(16) float shh[2][HID];       // double-buffered h (=2h)
    __shared__ volatile float s_sink;

    const int g = lane & 3;
    const int e = 8 * wid + (lane >> 2);

    // W_hh row (32g + e) -> registers (overlaps frame phase).
    const float wscale = (g == 2) ? 0.5f : 0.25f;
    float w[HID];
    {
        const float4* wr = reinterpret_cast<const float4*>(whh + (32 * g + e) * HID);
        #pragma unroll
        for (int k4 = 0; k4 < HID / 4; k4++) {
            float4 v = wr[k4];
            w[4 * k4 + 0] = v.x * wscale;
            w[4 * k4 + 1] = v.y * wscale;
            w[4 * k4 + 2] = v.z * wscale;
            w[4 * k4 + 3] = v.w * wscale;
        }
    }

    // head-weight L1 warm (off critical path, during frame phase)
    {
        float acc = 0.0f;
        #pragma unroll 4
        for (int i = tid * 8; i < 256 * 32; i += 128 * 8) acc += w12[i];
        for (int i = tid * 8; i < 32 * 32; i += 128 * 8) acc += w10[i] + w11[i];
        if (tid < 32) acc += b10[tid] + b11[tid] + bng[tid] + bnb[tid];
        if (tid < 64) acc += b12[tid * 4];
        s_sink = acc;
    }

    // ---- wait ONLY for frames 0..LEAD-1 (parallel flag poll, once) ----
    {
        int myf = 0;
        do {
            if (!myf) myf = ld_acquire_gpu(&g_flag[tid & (LEAD - 1)]);
        } while (!__syncthreads_and(myf));
        __threadfence();
    }
    // stage chunk A: frames [0, LEAD)
    {
        float4* s4 = reinterpret_cast<float4*>(sgx);
        const float4* g4 = reinterpret_cast<const float4*>(g_gx);
        #pragma unroll
        for (int i = tid; i < (LEAD * NG) / 4; i += 128)
            s4[i] = __ldcg(g4 + i);
    }
    __syncthreads();

    const int myslot = 32 * wid + lane;   // e*4+g, stride-1 per frame

    float c = 0.0f;                        // meaningful only in g==0 lanes

    // ---- t = 0 peeled ----
    {
        float a  = tanha(sgx[myslot]);
        float b  = __shfl_xor_sync(FULLM, a, 1);
        float d  = __shfl_xor_sync(FULLM, a, 2);
        float e4 = __shfl_xor_sync(FULLM, a, 3);
        (void)b;
        c = 0.5f * fmaf(a, d, d);
        float th = tanha(c);
        float hp = fmaf(e4, th, th);
        if (g == 0) shh[1][e] = hp;
        __syncthreads();
    }

    // ---- segment A: t = 1 .. LEAD-1 (overlaps frame blocks 16..59) ----
    #pragma unroll 1
    for (int t = 1; t < LEAD; t++) {
        const float* hv_buf = shh[t & 1];
        float acc[8];
        acc[0] = sgx[t * NG + myslot];
        #pragma unroll
        for (int i = 1; i < 8; i++) acc[i] = 0.0f;
        #pragma unroll
        for (int k4 = 0; k4 < 8; k4++) {
            float4 hv = *reinterpret_cast<const float4*>(&hv_buf[k4 * 4]);
            acc[k4] = fmaf(w[4 * k4 + 0], hv.x, acc[k4]);
            acc[k4] = fmaf(w[4 * k4 + 1], hv.y, acc[k4]);
            acc[k4] = fmaf(w[4 * k4 + 2], hv.z, acc[k4]);
            acc[k4] = fmaf(w[4 * k4 + 3], hv.w, acc[k4]);
        }
        float gs = ((acc[0] + acc[1]) + (acc[2] + acc[3]))
                 + ((acc[4] + acc[5]) + (acc[6] + acc[7]));
        float a  = tanha(gs);
        float b  = __shfl_xor_sync(FULLM, a, 1);
        float d  = __shfl_xor_sync(FULLM, a, 2);
        float e4 = __shfl_xor_sync(FULLM, a, 3);
        c = 0.5f * (fmaf(b, c, c) + fmaf(a, d, d));
        float th = tanha(c);
        float hp = fmaf(e4, th, th);
        if (g == 0) shh[(t + 1) & 1][e] = hp;
        __syncthreads();
    }

    // ---- ONE sync point: remaining frames done by now; stage chunk B ----
    if (tid == 0) {
        while (ld_acquire_gpu(&g_done) < T_FRAMES) { }
        __threadfence();
    }
    __syncthreads();
    {
        float4* s4 = reinterpret_cast<float4*>(sgx);
        const float4* g4 = reinterpret_cast<const float4*>(g_gx);
        #pragma unroll
        for (int i = (LEAD * NG) / 4 + tid; i < (T_FRAMES * NG) / 4; i += 128)
            s4[i] = __ldcg(g4 + i);
    }
    __syncthreads();

    // ---- segment B: t = LEAD .. T_FRAMES-1 ----
    #pragma unroll 1
    for (int t = LEAD; t < T_FRAMES; t++) {
        const float* hv_buf = shh[t & 1];
        float acc[8];
        acc[0] = sgx[t * NG + myslot];
        #pragma unroll
        for (int i = 1; i < 8; i++) acc[i] = 0.0f;
        #pragma unroll
        for (int k4 = 0; k4 < 8; k4++) {
            float4 hv = *reinterpret_cast<const float4*>(&hv_buf[k4 * 4]);
            acc[k4] = fmaf(w[4 * k4 + 0], hv.x, acc[k4]);
            acc[k4] = fmaf(w[4 * k4 + 1], hv.y, acc[k4]);
            acc[k4] = fmaf(w[4 * k4 + 2], hv.z, acc[k4]);
            acc[k4] = fmaf(w[4 * k4 + 3], hv.w, acc[k4]);
        }
        float gs = ((acc[0] + acc[1]) + (acc[2] + acc[3]))
                 + ((acc[4] + acc[5]) + (acc[6] + acc[7]));
        float a  = tanha(gs);
        float b  = __shfl_xor_sync(FULLM, a, 1);
        float d  = __shfl_xor_sync(FULLM, a, 2);
        float e4 = __shfl_xor_sync(FULLM, a, 3);
        c = 0.5f * (fmaf(b, c, c) + fmaf(a, d, d));
        float th = tanha(c);
        float hp = fmaf(e4, th, th);
        if (g == 0) shh[(t + 1) & 1][e] = hp;
        __syncthreads();
    }

    // ---- output head ----
    float h  = 0.5f * shh[T_FRAMES & 1][lane];
    float hb = (h * rsqrtf(1.0f + EPSF)) * bng[lane] + bnb[lane];

    float o1 = b10[lane];
    #pragma unroll
    for (int k = 0; k < 32; k++)
        o1 = fmaf(w10[lane * 32 + k], __shfl_sync(FULLM, hb, k), o1);
    o1 = fmaxf(o1, 0.0f);

    float o2 = b11[lane];
    #pragma unroll
    for (int k = 0; k < 32; k++)
        o2 = fmaf(w11[lane * 32 + k], __shfl_sync(FULLM, o1, k), o2);
    o2 = fmaxf(o2, 0.0f);

    const int r0 = wid * 64 + lane;
    const int r1 = r0 + 32;
    float a0 = b12[r0], a1 = b12[r1];
    #pragma unroll
    for (int k = 0; k < 32; k++) {
        float v = __shfl_sync(FULLM, o2, k);
        a0 = fmaf(w12[r0 * 32 + k], v, a0);
        a1 = fmaf(w12[r1 * 32 + k], v, a1);
    }
    out[r0] = a0;
    out[r1] = a1;

    // reset sync state for next graph replay
    __syncthreads();
    if (tid < LEAD) g_flag[tid] = 0;
    if (tid == 0) g_done = 0;
}

// ---------------------------------------------------------------------------
// Input order (metadata): x, w00, b00, w01, b01, ln_g, ln_b, w_ih, w_hh,
//                         b_ih, b_hh, bn_g, bn_b, w10, b10, w11, b11, w12, b12
// ---------------------------------------------------------------------------
extern "C" void kernel_launch(void* const* d_in, const int* in_sizes, int n_in,
                              void* d_out, int out_size)
{
    const float* x    = (const float*)d_in[0];
    const float* w00  = (const float*)d_in[1];
    const float* b00  = (const float*)d_in[2];
    const float* w01  = (const float*)d_in[3];
    const float* b01  = (const float*)d_in[4];
    const float* lng  = (const float*)d_in[5];
    const float* lnb  = (const float*)d_in[6];
    const float* wih  = (const float*)d_in[7];
    const float* whh  = (const float*)d_in[8];
    const float* bih  = (const float*)d_in[9];
    const float* bhh  = (const float*)d_in[10];
    const float* bng  = (const float*)d_in[11];
    const float* bnb  = (const float*)d_in[12];
    const float* w10  = (const float*)d_in[13];
    const float* b10  = (const float*)d_in[14];
    const float* w11  = (const float*)d_in[15];
    const float* b11  = (const float*)d_in[16];
    const float* w12  = (const float*)d_in[17];
    const float* b12  = (const float*)d_in[18];
    float* out = (float*)d_out;

    fused_kernel<<<T_FRAMES + 1, 128>>>(
        x, w00, b00, w01, b01, lng, lnb, wih, bih, bhh,
        whh, bng, bnb, w10, b10, w11, b11, w12, b12, out);
}

// round 15
// speedup vs baseline: 1.0702x; 1.0702x over previous
#include <cuda_runtime.h>

#define T_FRAMES 60
#define HID 32
#define NG 128          // 4*HID gate rows
#define EPSF 1e-5f
#define FULLM 0xffffffffu

// per-frame gate pre-activations, TRANSPOSED layout [t][e*4+g]
// (i/f/o entries pre-scaled by 0.5; g entries raw)
__device__ float g_gx[T_FRAMES * NG];
__device__ int   g_done = 0;

__device__ __forceinline__ float tanha(float x) {
    float r; asm("tanh.approx.f32 %0, %1;" : "=f"(r) : "f"(x)); return r;
}

// ---------------------------------------------------------------------------
// Fused kernel: blocks 0..59 = per-frame MLP+LN+W_ih matvec (parallel),
// block 60 = recurrence + output head. One wave (61 blocks < 148 SMs).
// ---------------------------------------------------------------------------
__global__ void __launch_bounds__(128, 1) fused_kernel(
    const float* __restrict__ x,
    const float* __restrict__ w00, const float* __restrict__ b00,
    const float* __restrict__ w01, const float* __restrict__ b01,
    const float* __restrict__ lng, const float* __restrict__ lnb,
    const float* __restrict__ wih, const float* __restrict__ bih,
    const float* __restrict__ bhh,
    const float* __restrict__ whh,
    const float* __restrict__ bng, const float* __restrict__ bnb,
    const float* __restrict__ w10, const float* __restrict__ b10,
    const float* __restrict__ w11, const float* __restrict__ b11,
    const float* __restrict__ w12, const float* __restrict__ b12,
    float* __restrict__ out)
{
    const int tid  = threadIdx.x;
    const int wid  = tid >> 5;
    const int lane = tid & 31;

    if (blockIdx.x < T_FRAMES) {
        // =================== frame path (parallel over t) ===================
        const int t = blockIdx.x;

        __shared__ float sx[64];
        __shared__ float sf1[64];
        __shared__ float sf2[64];
        __shared__ float sfn[64];
        __shared__ float s_mu, s_rstd;

        if (tid < 64) sx[tid] = (tid < 63) ? x[t * 63 + tid] : 0.0f;
        __syncthreads();

        // Layer 0: 63 rows, 2-way split-k (pair = adjacent lanes, same warp)
        {
            const int r    = tid >> 1;
            const int half = tid & 1;
            float acc = 0.0f;
            if (r < 63) {
                const float* wr = w00 + r * 63;
                if (half == 0) {
                    #pragma unroll
                    for (int k = 0; k < 32; k++) acc = fmaf(wr[k], sx[k], acc);
                } else {
                    #pragma unroll
                    for (int k = 32; k < 63; k++) acc = fmaf(wr[k], sx[k], acc);
                }
            }
            acc += __shfl_xor_sync(FULLM, acc, 1);
            if (r < 63 && half == 0) sf1[r] = fmaxf(acc + b00[r], 0.0f);
            if (tid == 126) sf1[63] = 0.0f;
        }
        __syncthreads();

        // Layer 1: 64 rows, 2-way split-k
        {
            const int r    = tid >> 1;
            const int half = tid & 1;
            const float* wr = w01 + r * 63;
            float acc = 0.0f;
            if (half == 0) {
                #pragma unroll
                for (int k = 0; k < 32; k++) acc = fmaf(wr[k], sf1[k], acc);
            } else {
                #pragma unroll
                for (int k = 32; k < 63; k++) acc = fmaf(wr[k], sf1[k], acc);
            }
            acc += __shfl_xor_sync(FULLM, acc, 1);
            if (half == 0) sf2[r] = fmaxf(acc + b01[r], 0.0f);
        }
        __syncthreads();

        if (tid < 32) {
            float v0 = sf2[tid], v1 = sf2[tid + 32];
            float s = v0 + v1;
            float q = v0 * v0 + v1 * v1;
            #pragma unroll
            for (int o = 16; o > 0; o >>= 1) {
                s += __shfl_xor_sync(FULLM, s, o);
                q += __shfl_xor_sync(FULLM, q, o);
            }
            if (tid == 0) {
                float mu  = s * (1.0f / 64.0f);
                float var = q * (1.0f / 64.0f) - mu * mu;
                s_mu   = mu;
                s_rstd = rsqrtf(var + EPSF);
            }
        }
        __syncthreads();

        if (tid < 64)
            sfn[tid] = (sf2[tid] - s_mu) * s_rstd * lng[tid] + lnb[tid];
        __syncthreads();

        {
            float acc = bih[tid] + bhh[tid];
            const float* wr = wih + tid * 64;
            #pragma unroll
            for (int k = 0; k < 64; k++) acc = fmaf(wr[k], sfn[k], acc);
            const int gr = tid >> 5;
            float scale = (gr == 2) ? 1.0f : 0.5f;
            g_gx[t * NG + (tid & 31) * 4 + gr] = acc * scale;  // transposed
        }
        __syncthreads();
        if (tid == 0) {
            __threadfence();
            atomicAdd(&g_done, 1);
        }
        return;
    }

    // ======================= sequential path (block 60) =====================
    // lane mapping: element e = 8*wid + (lane>>2), gate g = lane&3.
    // Warp w owns all four gates of its 8 elements; c/h update is warp-local
    // (3 parallel shfl_xor); only h crosses warps (one STS + one BAR / step).
    __shared__ float sgx[T_FRAMES * NG];              // 30 KB staged gx
    __shared__ __align__(16) float shh[2][HID];       // double-buffered h (=2h)
    __shared__ volatile float s_sink;

    const int g = lane & 3;
    const int e = 8 * wid + (lane >> 2);

    // W_hh row (32g + e) -> registers (overlaps frame phase).
    // fold: x0.5 sigmoid half-arg (i/f/o) and x0.5 for hp = 2h publish.
    const float wscale = (g == 2) ? 0.5f : 0.25f;
    float w[HID];
    {
        const float4* wr = reinterpret_cast<const float4*>(whh + (32 * g + e) * HID);
        #pragma unroll
        for (int k4 = 0; k4 < HID / 4; k4++) {
            float4 v = wr[k4];
            w[4 * k4 + 0] = v.x * wscale;
            w[4 * k4 + 1] = v.y * wscale;
            w[4 * k4 + 2] = v.z * wscale;
            w[4 * k4 + 3] = v.w * wscale;
        }
    }

    // head-weight L1 warm (off critical path, during frame phase)
    {
        float acc = 0.0f;
        #pragma unroll 4
        for (int i = tid * 8; i < 256 * 32; i += 128 * 8) acc += w12[i];
        for (int i = tid * 8; i < 32 * 32; i += 128 * 8) acc += w10[i] + w11[i];
        if (tid < 32) acc += b10[tid] + b11[tid] + bng[tid] + bnb[tid];
        if (tid < 64) acc += b12[tid * 4];
        s_sink = acc;
    }

    // wait for all frame blocks
    if (tid == 0) {
        volatile int* p = &g_done;
        while (*p < T_FRAMES) { }
        __threadfence();
    }
    __syncthreads();

    // bulk-stage gx into smem (L2 -> smem)
    {
        float4* s4 = reinterpret_cast<float4*>(sgx);
        const float4* g4 = reinterpret_cast<const float4*>(g_gx);
        #pragma unroll
        for (int i = tid; i < (T_FRAMES * NG) / 4; i += 128)
            s4[i] = __ldcg(g4 + i);
    }
    __syncthreads();

    // this thread's gx slot per frame: e*4+g == 32*wid + lane (stride-1)
    const int myslot = 32 * wid + lane;

    float c = 0.0f;        // meaningful only in g==0 lanes

    // ---- t = 0 peeled: h = 0 -> pre-activation is just gx[0] ----
    {
        float a  = tanha(sgx[myslot]);
        float b  = __shfl_xor_sync(FULLM, a, 1);
        float d  = __shfl_xor_sync(FULLM, a, 2);
        float e4 = __shfl_xor_sync(FULLM, a, 3);
        (void)b;
        c = 0.5f * fmaf(a, d, d);            // sigma_i * tanh_g (c0 = 0)
        float th = tanha(c);
        float hp = fmaf(e4, th, th);         // 2h
        if (g == 0) shh[1][e] = hp;
    }
    // prefetch gx for t=1 BEFORE the barrier (keeps LDS off the post-BAR chain)
    float gxn = sgx[1 * NG + myslot];
    __syncthreads();

    #pragma unroll 1
    for (int t = 1; t < T_FRAMES; t++) {
        const float* hv_buf = shh[t & 1];
        float acc[8];
        acc[0] = gxn;                        // gx was prefetched last step
        #pragma unroll
        for (int i = 1; i < 8; i++) acc[i] = 0.0f;

        #pragma unroll
        for (int k4 = 0; k4 < 8; k4++) {
            float4 hv = *reinterpret_cast<const float4*>(&hv_buf[k4 * 4]); // broadcast
            acc[k4] = fmaf(w[4 * k4 + 0], hv.x, acc[k4]);
            acc[k4] = fmaf(w[4 * k4 + 1], hv.y, acc[k4]);
            acc[k4] = fmaf(w[4 * k4 + 2], hv.z, acc[k4]);
            acc[k4] = fmaf(w[4 * k4 + 3], hv.w, acc[k4]);
        }
        float gs = ((acc[0] + acc[1]) + (acc[2] + acc[3]))
                 + ((acc[4] + acc[5]) + (acc[6] + acc[7]));

        float a  = tanha(gs);
        float b  = __shfl_xor_sync(FULLM, a, 1);   // 3 parallel shuffles
        float d  = __shfl_xor_sync(FULLM, a, 2);
        float e4 = __shfl_xor_sync(FULLM, a, 3);

        // lane g==0: a=ti, b=tf, d=tg, e4=to (others compute dead values)
        c = 0.5f * (fmaf(b, c, c) + fmaf(a, d, d));
        float th = tanha(c);
        float hp = fmaf(e4, th, th);               // 2h

        // branch-free prefetch of next step's gx (issued pre-BAR)
        int tn = (t + 1 < T_FRAMES) ? (t + 1) : t;
        gxn = sgx[tn * NG + myslot];

        if (g == 0) shh[(t + 1) & 1][e] = hp;      // ONE exchange per step
        __syncthreads();                           // ONE barrier per step
    }

    // ---- output head ----
    float h  = 0.5f * shh[T_FRAMES & 1][lane];
    float hb = (h * rsqrtf(1.0f + EPSF)) * bng[lane] + bnb[lane];

    float o1 = b10[lane];
    #pragma unroll
    for (int k = 0; k < 32; k++)
        o1 = fmaf(w10[lane * 32 + k], __shfl_sync(FULLM, hb, k), o1);
    o1 = fmaxf(o1, 0.0f);

    float o2 = b11[lane];
    #pragma unroll
    for (int k = 0; k < 32; k++)
        o2 = fmaf(w11[lane * 32 + k], __shfl_sync(FULLM, o1, k), o2);
    o2 = fmaxf(o2, 0.0f);

    // warp w -> output rows [64w, 64w+64): 2 rows per lane
    const int r0 = wid * 64 + lane;
    const int r1 = r0 + 32;
    float a0 = b12[r0], a1 = b12[r1];
    #pragma unroll
    for (int k = 0; k < 32; k++) {
        float v = __shfl_sync(FULLM, o2, k);
        a0 = fmaf(w12[r0 * 32 + k], v, a0);
        a1 = fmaf(w12[r1 * 32 + k], v, a1);
    }
    out[r0] = a0;
    out[r1] = a1;

    // reset counter for next replay
    __syncthreads();
    if (tid == 0) g_done = 0;
}

// ---------------------------------------------------------------------------
// Input order (metadata): x, w00, b00, w01, b01, ln_g, ln_b, w_ih, w_hh,
//                         b_ih, b_hh, bn_g, bn_b, w10, b10, w11, b11, w12, b12
// ---------------------------------------------------------------------------
extern "C" void kernel_launch(void* const* d_in, const int* in_sizes, int n_in,
                              void* d_out, int out_size)
{
    const float* x    = (const float*)d_in[0];
    const float* w00  = (const float*)d_in[1];
    const float* b00  = (const float*)d_in[2];
    const float* w01  = (const float*)d_in[3];
    const float* b01  = (const float*)d_in[4];
    const float* lng  = (const float*)d_in[5];
    const float* lnb  = (const float*)d_in[6];
    const float* wih  = (const float*)d_in[7];
    const float* whh  = (const float*)d_in[8];
    const float* bih  = (const float*)d_in[9];
    const float* bhh  = (const float*)d_in[10];
    const float* bng  = (const float*)d_in[11];
    const float* bnb  = (const float*)d_in[12];
    const float* w10  = (const float*)d_in[13];
    const float* b10  = (const float*)d_in[14];
    const float* w11  = (const float*)d_in[15];
    const float* b11  = (const float*)d_in[16];
    const float* w12  = (const float*)d_in[17];
    const float* b12  = (const float*)d_in[18];
    float* out = (float*)d_out;

    fused_kernel<<<T_FRAMES + 1, 128>>>(
        x, w00, b00, w01, b01, lng, lnb, wih, bih, bhh,
        whh, bng, bnb, w10, b10, w11, b11, w12, b12, out);
}